// round 1
// baseline (speedup 1.0000x reference)
#include <cuda_runtime.h>
#include <cstdint>

// Problem constants
#define BATCH   256
#define DIN     5120
#define RNK     160
#define NST     16
#define NOUT    192   // 160 (dt_low) + 16 (Bp) + 16 (C)

// Scratch: P^T layout [out(192)][batch(256)]
__device__ float g_Pt[NOUT * BATCH];

// ---------- f32x2 helpers ----------
__device__ __forceinline__ unsigned long long pack2(float lo, float hi) {
    unsigned long long r;
    asm("mov.b64 %0, {%1, %2};" : "=l"(r)
        : "r"(__float_as_uint(lo)), "r"(__float_as_uint(hi)));
    return r;
}
__device__ __forceinline__ void unpack2(unsigned long long v, float& lo, float& hi) {
    unsigned int a, b;
    asm("mov.b64 {%0, %1}, %2;" : "=r"(a), "=r"(b) : "l"(v));
    lo = __uint_as_float(a);
    hi = __uint_as_float(b);
}
__device__ __forceinline__ void ffma2(unsigned long long& d,
                                      unsigned long long a,
                                      unsigned long long b) {
    asm("fma.rn.f32x2 %0, %1, %2, %0;" : "+l"(d) : "l"(a), "l"(b));
}
__device__ __forceinline__ float ex2f(float x) {
    float r;
    asm("ex2.approx.ftz.f32 %0, %1;" : "=f"(r) : "f"(x));
    return r;
}

// ---------- K0: zero the P scratch ----------
__global__ void k0_zero() {
    int i = blockIdx.x * blockDim.x + threadIdx.x;
    if (i < NOUT * BATCH) g_Pt[i] = 0.0f;
}

// ---------- K1: P^T[j][b] = sum_d x[b,d] * Wcat[d,j]  (split-K, atomicAdd) ----------
// grid (40 k-splits, 4 batch-tiles), block 256.
// smem: Xs[64][132] (pad), Ws[128][192]. 129 KB dynamic.
#define K1_KC 128
#define K1_BT 64
#define K1_XPAD 132
#define K1_SMEM ((K1_BT * K1_XPAD + K1_KC * NOUT) * 4)

__global__ __launch_bounds__(256, 1)
void k1_proj(const float* __restrict__ x,
             const float* __restrict__ Wd,
             const float* __restrict__ WB,
             const float* __restrict__ WC) {
    extern __shared__ float sm[];
    float* Xs = sm;                     // 64 x 132
    float* Ws = sm + K1_BT * K1_XPAD;   // 128 x 192

    const int t  = threadIdx.x;
    const int k0 = blockIdx.x * K1_KC;
    const int b0 = blockIdx.y * K1_BT;

    // load X tile (coalesced float4, no transpose)
    for (int e = t; e < K1_BT * (K1_KC / 4); e += 256) {
        int row = e >> 5;          // 32 quads per row
        int q   = e & 31;
        float4 v = *(const float4*)&x[(b0 + row) * DIN + k0 + q * 4];
        *(float4*)&Xs[row * K1_XPAD + q * 4] = v;
    }
    // load concatenated W tile: rows k, cols [Wd(160) | WB(16) | WC(16)]
    for (int e = t; e < K1_KC * NOUT; e += 256) {
        int k = e / NOUT;
        int j = e - k * NOUT;
        int kk = k0 + k;
        float v;
        if (j < RNK)       v = Wd[kk * RNK + j];
        else if (j < 176)  v = WB[kk * NST + (j - 160)];
        else               v = WC[kk * NST + (j - 176)];
        Ws[k * NOUT + j] = v;
    }
    __syncthreads();

    const int og = t & 15;   // out group: 12 outputs
    const int bg = t >> 4;   // batch group: 4 batches
    const int wbase = og * 12;

    unsigned long long acc[4][6];
#pragma unroll
    for (int i = 0; i < 4; i++)
#pragma unroll
        for (int p = 0; p < 6; p++) acc[i][p] = 0ull;

#pragma unroll 4
    for (int k = 0; k < K1_KC; k++) {
        const ulonglong2* wp = (const ulonglong2*)&Ws[k * NOUT + wbase];
        ulonglong2 w0 = wp[0], w1 = wp[1], w2 = wp[2];
        unsigned long long wpair[6] = {w0.x, w0.y, w1.x, w1.y, w2.x, w2.y};
#pragma unroll
        for (int i = 0; i < 4; i++) {
            float xv = Xs[(bg * 4 + i) * K1_XPAD + k];
            unsigned long long x2 = pack2(xv, xv);
#pragma unroll
            for (int p = 0; p < 6; p++) ffma2(acc[i][p], x2, wpair[p]);
        }
    }

#pragma unroll
    for (int i = 0; i < 4; i++) {
        int b = b0 + bg * 4 + i;
#pragma unroll
        for (int p = 0; p < 6; p++) {
            float lo, hi;
            unpack2(acc[i][p], lo, hi);
            int j = wbase + p * 2;
            atomicAdd(&g_Pt[j * BATCH + b], lo);
            atomicAdd(&g_Pt[(j + 1) * BATCH + b], hi);
        }
    }
}

// ---------- K2: dt GEMM + softplus + SSM elementwise + readout ----------
// grid (80 d-chunks of 64, 4 batch-tiles of 64), block 256, 2 CTAs/SM.
#define K2_DC 64
#define K2_BT 64
// smem floats: Wdt 160*64, Ps 160*64, As2 64*17, Cs 16*64, Bs 16*64, Ds 64, Bds 64
#define K2_SMEM ((RNK*K2_DC + RNK*K2_BT + K2_DC*17 + NST*K2_BT*2 + K2_DC*2) * 4)

__global__ __launch_bounds__(256, 2)
void k2_ssm(const float* __restrict__ x,
            const float* __restrict__ h,
            const float* __restrict__ Wdt,
            const float* __restrict__ bdt,
            const float* __restrict__ Alog,
            const float* __restrict__ Dv,
            float* __restrict__ out) {
    extern __shared__ float sm[];
    float* Wds = sm;                       // [r][dj]  160 x 64
    float* Ps  = Wds + RNK * K2_DC;        // [r][bi]  160 x 64
    float* As2 = Ps + RNK * K2_BT;         // [dj][17] : -exp(A_log)*log2e
    float* Bs  = As2 + K2_DC * 17;         // [n][bi]  16 x 64
    float* Cs  = Bs + NST * K2_BT;         // [n][bi]  16 x 64
    float* Ds  = Cs + NST * K2_BT;         // [dj]
    float* Bds = Ds + K2_DC;               // [dj] (b_dt)

    const int t  = threadIdx.x;
    const int d0 = blockIdx.x * K2_DC;
    const int b0 = blockIdx.y * K2_BT;

    // load W_dt tile [r][d0..d0+63] and P tile [r][b0..b0+63]
    for (int e = t; e < RNK * 16; e += 256) {
        int r = e >> 4, q = e & 15;
        *(float4*)&Wds[r * K2_DC + q * 4] =
            *(const float4*)&Wdt[r * DIN + d0 + q * 4];
        *(float4*)&Ps[r * K2_BT + q * 4] =
            *(const float4*)&g_Pt[r * BATCH + b0 + q * 4];
    }
    // As2: -exp(A_log)*log2e, padded stride 17
    {
        int dj = t >> 2, q = t & 3;   // 256 threads cover 64*4 quads
        float4 a = *(const float4*)&Alog[(d0 + dj) * NST + q * 4];
        const float c = -1.44269504088896f;
        As2[dj * 17 + q * 4 + 0] = c * __expf(a.x);
        As2[dj * 17 + q * 4 + 1] = c * __expf(a.y);
        As2[dj * 17 + q * 4 + 2] = c * __expf(a.z);
        As2[dj * 17 + q * 4 + 3] = c * __expf(a.w);
    }
    // Bp / C tiles: rows 160..175 / 176..191 of P^T, [n][bi] layout
    {
        int n = t >> 4, q = t & 15;   // 256 threads = 16 n x 16 quads
        *(float4*)&Bs[n * K2_BT + q * 4] =
            *(const float4*)&g_Pt[(160 + n) * BATCH + b0 + q * 4];
        *(float4*)&Cs[n * K2_BT + q * 4] =
            *(const float4*)&g_Pt[(176 + n) * BATCH + b0 + q * 4];
    }
    if (t < K2_DC) {
        Ds[t]  = Dv[d0 + t];
        Bds[t] = bdt[d0 + t];
    }
    __syncthreads();

    const int tx = t & 15;   // d group (4 d)
    const int ty = t >> 4;   // batch group (4 b)

    // ---- Phase A: dt[b][d] = softplus( sum_r P[r][b] * Wdt[r][d] + b_dt[d] )
    unsigned long long acc[4][2];
#pragma unroll
    for (int i = 0; i < 4; i++) { acc[i][0] = 0ull; acc[i][1] = 0ull; }

#pragma unroll 4
    for (int r = 0; r < RNK; r++) {
        ulonglong2 w = *(const ulonglong2*)&Wds[r * K2_DC + tx * 4];
#pragma unroll
        for (int i = 0; i < 4; i++) {
            float p = Ps[r * K2_BT + ty * 4 + i];
            unsigned long long p2 = pack2(p, p);
            ffma2(acc[i][0], p2, w.x);
            ffma2(acc[i][1], p2, w.y);
        }
    }

    float dtm[4][4];
#pragma unroll
    for (int i = 0; i < 4; i++) {
#pragma unroll
        for (int pj = 0; pj < 2; pj++) {
            float z0, z1;
            unpack2(acc[i][pj], z0, z1);
            int dj = tx * 4 + pj * 2;
            z0 += Bds[dj];
            z1 += Bds[dj + 1];
            // softplus with threshold 20 (stable form)
            dtm[i][pj * 2]     = (z0 > 20.0f) ? z0
                : fmaxf(z0, 0.0f) + log1pf(__expf(-fabsf(z0)));
            dtm[i][pj * 2 + 1] = (z1 > 20.0f) ? z1
                : fmaxf(z1, 0.0f) + log1pf(__expf(-fabsf(z1)));
        }
    }

    // per-batch sum_n Bp[n]*C[n]
    float SBC[4];
#pragma unroll
    for (int i = 0; i < 4; i++) {
        int bi = ty * 4 + i;
        float s = 0.0f;
#pragma unroll
        for (int n = 0; n < NST; n++)
            s = fmaf(Bs[n * K2_BT + bi], Cs[n * K2_BT + bi], s);
        SBC[i] = s;
    }

    // ---- Phase B: stream h, produce y
#pragma unroll
    for (int j = 0; j < 4; j++) {
        const int dj = tx * 4 + j;
        const int d  = d0 + dj;
        float a2[NST];
#pragma unroll
        for (int n = 0; n < NST; n++) a2[n] = As2[dj * 17 + n];
        const float Dd = Ds[dj];
#pragma unroll
        for (int i = 0; i < 4; i++) {
            const int bi = ty * 4 + i;
            const int b  = b0 + bi;
            const float dtv = dtm[i][j];
            const float xv  = x[b * DIN + d];
            const float dtx = dtv * xv;
            float y = fmaf(dtx, SBC[i], xv * Dd);
            const float4* hp = (const float4*)&h[((size_t)(b * DIN + d)) * NST];
            float4 h4[4] = {hp[0], hp[1], hp[2], hp[3]};
            const float* hv = (const float*)h4;
#pragma unroll
            for (int n = 0; n < NST; n++) {
                float ab = ex2f(dtv * a2[n]);
                y = fmaf(Cs[n * K2_BT + bi], ab * hv[n], y);
            }
            out[b * DIN + d] = y;
        }
    }
}

// ---------- launch ----------
extern "C" void kernel_launch(void* const* d_in, const int* in_sizes, int n_in,
                              void* d_out, int out_size) {
    const float* x    = (const float*)d_in[0];
    const float* h    = (const float*)d_in[1];
    const float* Wd   = (const float*)d_in[2];
    const float* Wdt  = (const float*)d_in[3];
    const float* bdt  = (const float*)d_in[4];
    const float* Alog = (const float*)d_in[5];
    const float* WB   = (const float*)d_in[6];
    const float* WC   = (const float*)d_in[7];
    const float* Dv   = (const float*)d_in[8];
    float* out = (float*)d_out;

    cudaFuncSetAttribute(k1_proj, cudaFuncAttributeMaxDynamicSharedMemorySize, K1_SMEM);
    cudaFuncSetAttribute(k2_ssm,  cudaFuncAttributeMaxDynamicSharedMemorySize, K2_SMEM);

    k0_zero<<<(NOUT * BATCH + 1023) / 1024, 1024>>>();
    k1_proj<<<dim3(DIN / K1_KC, BATCH / K1_BT), 256, K1_SMEM>>>(x, Wd, WB, WC);
    k2_ssm<<<dim3(DIN / K2_DC, BATCH / K2_BT), 256, K2_SMEM>>>(
        x, h, Wdt, bdt, Alog, Dv, out);
}

// round 2
// speedup vs baseline: 1.3578x; 1.3578x over previous
#include <cuda_runtime.h>
#include <cstdint>

#define BATCH   256
#define DIN     5120
#define RNK     160
#define NST     16
#define NOUT    192   // 160 (dt_low) + 16 (Bp) + 16 (C)

// Scratch
__device__ float g_Pt[NOUT * BATCH];        // P^T [out][batch]
__device__ float g_dt[BATCH * DIN];         // softplus'd delta [b][d]
__device__ float g_As2[DIN * NST];          // -exp(A_log)*log2e
__device__ float g_Ct[BATCH * NST];         // C transposed [b][n]
__device__ float g_SBC[BATCH];              // sum_n Bp*C per batch

// ---------- f32x2 helpers ----------
__device__ __forceinline__ unsigned long long pack2(float lo, float hi) {
    unsigned long long r;
    asm("mov.b64 %0, {%1, %2};" : "=l"(r)
        : "r"(__float_as_uint(lo)), "r"(__float_as_uint(hi)));
    return r;
}
__device__ __forceinline__ void unpack2(unsigned long long v, float& lo, float& hi) {
    unsigned int a, b;
    asm("mov.b64 {%0, %1}, %2;" : "=r"(a), "=r"(b) : "l"(v));
    lo = __uint_as_float(a);
    hi = __uint_as_float(b);
}
__device__ __forceinline__ void ffma2(unsigned long long& d,
                                      unsigned long long a,
                                      unsigned long long b) {
    asm("fma.rn.f32x2 %0, %1, %2, %0;" : "+l"(d) : "l"(a), "l"(b));
}
__device__ __forceinline__ float ex2f(float x) {
    float r;
    asm("ex2.approx.ftz.f32 %0, %1;" : "=f"(r) : "f"(x));
    return r;
}
__device__ __forceinline__ float softplus20(float z) {
    return (z > 20.0f) ? z : fmaxf(z, 0.0f) + log1pf(__expf(-fabsf(z)));
}

// ---------- K0: zero P + precompute As2 ----------
__global__ void k0_init(const float* __restrict__ Alog) {
    int i = blockIdx.x * blockDim.x + threadIdx.x;
    if (i < NOUT * BATCH) g_Pt[i] = 0.0f;
    if (i < DIN * NST)
        g_As2[i] = -1.44269504088896f * __expf(Alog[i]);
}

// ---------- K1: P^T[j][b] += sum_k x[b,k] * Wcat[k,j] ----------
// grid (32 ksplits of 160, 4 btiles of 64), block 256 = 8 warps.
// Warp w handles 24 outputs [w*24, w*24+24); lane handles batches lane, lane+32.
#define K1_KC 160
#define K1_BT 64
#define K1_SMEM ((K1_KC * 65 + K1_KC * NOUT) * 4)

__global__ __launch_bounds__(256, 1)
void k1_proj(const float* __restrict__ x,
             const float* __restrict__ Wd,
             const float* __restrict__ WB,
             const float* __restrict__ WC) {
    extern __shared__ float sm[];
    float* Xst = sm;                 // [k][b] 160 x 65 (pad)
    float* Ws  = sm + K1_KC * 65;    // [k][j] 160 x 192

    const int t  = threadIdx.x;
    const int k0 = blockIdx.x * K1_KC;
    const int b0 = blockIdx.y * K1_BT;

    // load X transposed: 64 rows x 40 quads
    for (int e = t; e < K1_BT * (K1_KC / 4); e += 256) {
        int row = e / 40;
        int q   = e - row * 40;
        float4 v = *(const float4*)&x[(b0 + row) * DIN + k0 + q * 4];
        int base = (q * 4) * 65 + row;
        Xst[base]       = v.x;
        Xst[base + 65]  = v.y;
        Xst[base + 130] = v.z;
        Xst[base + 195] = v.w;
    }
    // load W concatenated: 160 rows x 48 quads
    for (int e = t; e < K1_KC * 48; e += 256) {
        int k  = e / 48;
        int j4 = (e - k * 48) * 4;
        int kk = k0 + k;
        float4 v;
        if (j4 < RNK)      v = *(const float4*)&Wd[kk * RNK + j4];
        else if (j4 < 176) v = *(const float4*)&WB[kk * NST + (j4 - 160)];
        else               v = *(const float4*)&WC[kk * NST + (j4 - 176)];
        *(float4*)&Ws[k * NOUT + j4] = v;
    }
    __syncthreads();

    const int w    = t >> 5;
    const int lane = t & 31;
    const int jb   = w * 24;

    unsigned long long acc[2][12];
#pragma unroll
    for (int i = 0; i < 2; i++)
#pragma unroll
        for (int j = 0; j < 12; j++) acc[i][j] = 0ull;

#pragma unroll 2
    for (int k = 0; k < K1_KC; k++) {
        const ulonglong2* wp = (const ulonglong2*)&Ws[k * NOUT + jb];
        ulonglong2 w0 = wp[0], w1 = wp[1], w2 = wp[2];
        ulonglong2 w3 = wp[3], w4 = wp[4], w5 = wp[5];
        unsigned long long wr[12] = {w0.x, w0.y, w1.x, w1.y, w2.x, w2.y,
                                     w3.x, w3.y, w4.x, w4.y, w5.x, w5.y};
        float xa = Xst[k * 65 + lane];
        float xb = Xst[k * 65 + 32 + lane];
        unsigned long long xa2 = pack2(xa, xa);
        unsigned long long xb2 = pack2(xb, xb);
#pragma unroll
        for (int j = 0; j < 12; j++) {
            ffma2(acc[0][j], xa2, wr[j]);
            ffma2(acc[1][j], xb2, wr[j]);
        }
    }

#pragma unroll
    for (int j = 0; j < 12; j++) {
        float lo, hi;
        int jj = jb + j * 2;
        unpack2(acc[0][j], lo, hi);
        atomicAdd(&g_Pt[jj * BATCH + b0 + lane], lo);
        atomicAdd(&g_Pt[(jj + 1) * BATCH + b0 + lane], hi);
        unpack2(acc[1][j], lo, hi);
        atomicAdd(&g_Pt[jj * BATCH + b0 + 32 + lane], lo);
        atomicAdd(&g_Pt[(jj + 1) * BATCH + b0 + 32 + lane], hi);
    }
}

// ---------- K2: dt = softplus(P_low @ W_dt + b_dt); also Ct + SBC scratch ----------
// grid (80 dchunks of 64, 4 btiles of 64), block 256, 2 CTAs/SM.
#define K2_SMEM ((RNK * 64 * 2 + 64) * 4)

__global__ __launch_bounds__(256, 2)
void k2_dt(const float* __restrict__ Wdt,
           const float* __restrict__ bdt) {
    extern __shared__ float sm[];
    float* Wds = sm;                 // [r][dj] 160 x 64
    float* Ps  = sm + RNK * 64;      // [r][bi] 160 x 64
    float* Bds = sm + RNK * 128;     // [dj]

    const int t  = threadIdx.x;
    const int d0 = blockIdx.x * 64;
    const int b0 = blockIdx.y * 64;

    for (int e = t; e < RNK * 16; e += 256) {
        int r = e >> 4, q = e & 15;
        *(float4*)&Wds[r * 64 + q * 4] = *(const float4*)&Wdt[r * DIN + d0 + q * 4];
        *(float4*)&Ps[r * 64 + q * 4]  = *(const float4*)&g_Pt[r * BATCH + b0 + q * 4];
    }
    if (t < 64) Bds[t] = bdt[d0 + t];
    __syncthreads();

    const int tx = t & 15;   // dj group of 4
    const int ty = t >> 4;   // bi group of 4

    unsigned long long acc[4][2];
#pragma unroll
    for (int i = 0; i < 4; i++) { acc[i][0] = 0ull; acc[i][1] = 0ull; }

#pragma unroll 2
    for (int r = 0; r < RNK; r++) {
        ulonglong2 wv = *(const ulonglong2*)&Wds[r * 64 + tx * 4];
        float4 p4 = *(const float4*)&Ps[r * 64 + ty * 4];
        float pv[4] = {p4.x, p4.y, p4.z, p4.w};
#pragma unroll
        for (int i = 0; i < 4; i++) {
            unsigned long long p2 = pack2(pv[i], pv[i]);
            ffma2(acc[i][0], p2, wv.x);
            ffma2(acc[i][1], p2, wv.y);
        }
    }

    float bb0 = Bds[tx * 4], bb1 = Bds[tx * 4 + 1];
    float bb2 = Bds[tx * 4 + 2], bb3 = Bds[tx * 4 + 3];
#pragma unroll
    for (int i = 0; i < 4; i++) {
        float z0, z1, z2, z3;
        unpack2(acc[i][0], z0, z1);
        unpack2(acc[i][1], z2, z3);
        float4 dt4;
        dt4.x = softplus20(z0 + bb0);
        dt4.y = softplus20(z1 + bb1);
        dt4.z = softplus20(z2 + bb2);
        dt4.w = softplus20(z3 + bb3);
        *(float4*)&g_dt[(b0 + ty * 4 + i) * DIN + d0 + tx * 4] = dt4;
    }

    // one CTA column also materializes Ct and SBC for its b-tile
    if (blockIdx.x == 0) {
        for (int e = t; e < 64 * NST; e += 256) {
            int bi = e >> 4, n = e & 15;
            g_Ct[(b0 + bi) * NST + n] = g_Pt[(176 + n) * BATCH + b0 + bi];
        }
        if (t < 64) {
            float s = 0.0f;
#pragma unroll
            for (int n = 0; n < NST; n++)
                s = fmaf(g_Pt[(160 + n) * BATCH + b0 + t],
                         g_Pt[(176 + n) * BATCH + b0 + t], s);
            g_SBC[b0 + t] = s;
        }
    }
}

// ---------- K3: stream h, produce y (warp-cooperative, coalesced) ----------
// group = (b, 8 consecutive d). 4 lanes per (b,d), lane q covers n = q*4..q*4+3.
#define NGRP (BATCH * DIN / 8)   // 163840
#define K3_GRID 592

__global__ __launch_bounds__(256)
void k3_stream(const float* __restrict__ h,
               const float* __restrict__ x,
               const float* __restrict__ Dv,
               float* __restrict__ out) {
    const int t     = threadIdx.x;
    const int lane  = t & 31;
    const int p     = lane >> 2;
    const int q     = lane & 3;
    const int wglob = blockIdx.x * 8 + (t >> 5);
    const int nw    = K3_GRID * 8;

    for (int g = wglob; g < NGRP; g += nw) {
        int b = g / 640;
        int c = g - b * 640;
        int d = c * 8 + p;

        float4 hv = *(const float4*)&h[((size_t)b * DIN + d) * NST + q * 4];
        float4 a4 = *(const float4*)&g_As2[d * NST + q * 4];
        float4 c4 = *(const float4*)&g_Ct[b * NST + q * 4];
        float dtv = g_dt[b * DIN + d];

        float e0 = ex2f(dtv * a4.x);
        float e1 = ex2f(dtv * a4.y);
        float e2 = ex2f(dtv * a4.z);
        float e3 = ex2f(dtv * a4.w);

        float s = c4.x * (e0 * hv.x);
        s = fmaf(c4.y, e1 * hv.y, s);
        s = fmaf(c4.z, e2 * hv.z, s);
        s = fmaf(c4.w, e3 * hv.w, s);

        s += __shfl_xor_sync(0xffffffffu, s, 1);
        s += __shfl_xor_sync(0xffffffffu, s, 2);

        if (q == 0) {
            float xv = x[b * DIN + d];
            float base = xv * fmaf(dtv, g_SBC[b], Dv[d]);
            out[b * DIN + d] = s + base;
        }
    }
}

// ---------- launch ----------
extern "C" void kernel_launch(void* const* d_in, const int* in_sizes, int n_in,
                              void* d_out, int out_size) {
    const float* x    = (const float*)d_in[0];
    const float* h    = (const float*)d_in[1];
    const float* Wd   = (const float*)d_in[2];
    const float* Wdt  = (const float*)d_in[3];
    const float* bdt  = (const float*)d_in[4];
    const float* Alog = (const float*)d_in[5];
    const float* WB   = (const float*)d_in[6];
    const float* WC   = (const float*)d_in[7];
    const float* Dv   = (const float*)d_in[8];
    float* out = (float*)d_out;

    cudaFuncSetAttribute(k1_proj, cudaFuncAttributeMaxDynamicSharedMemorySize, K1_SMEM);
    cudaFuncSetAttribute(k2_dt,   cudaFuncAttributeMaxDynamicSharedMemorySize, K2_SMEM);

    k0_init<<<(DIN * NST + 255) / 256, 256>>>(Alog);
    k1_proj<<<dim3(DIN / K1_KC, BATCH / K1_BT), 256, K1_SMEM>>>(x, Wd, WB, WC);
    k2_dt<<<dim3(DIN / 64, BATCH / 64), 256, K2_SMEM>>>(Wdt, bdt);
    k3_stream<<<K3_GRID, 256>>>(h, x, Dv, out);
}

// round 3
// speedup vs baseline: 1.6425x; 1.2097x over previous
#include <cuda_runtime.h>
#include <cstdint>

#define BATCH   256
#define DIN     5120
#define RNK     160
#define NST     16
#define NOUT    192   // 160 (dt_low) + 16 (Bp) + 16 (C)

// Scratch
__device__ float g_Pt[NOUT * BATCH];        // P^T [out][batch]
__device__ float g_dt[BATCH * DIN];         // softplus'd delta [b][d]
__device__ float g_As2[DIN * NST];          // -exp(A_log)*log2e
__device__ float g_Ct[BATCH * NST];         // C transposed [b][n]
__device__ float g_SBC[BATCH];              // sum_n Bp*C per batch

// ---------- f32x2 helpers ----------
__device__ __forceinline__ unsigned long long pack2(float lo, float hi) {
    unsigned long long r;
    asm("mov.b64 %0, {%1, %2};" : "=l"(r)
        : "r"(__float_as_uint(lo)), "r"(__float_as_uint(hi)));
    return r;
}
__device__ __forceinline__ void unpack2(unsigned long long v, float& lo, float& hi) {
    unsigned int a, b;
    asm("mov.b64 {%0, %1}, %2;" : "=r"(a), "=r"(b) : "l"(v));
    lo = __uint_as_float(a);
    hi = __uint_as_float(b);
}
__device__ __forceinline__ void ffma2(unsigned long long& d,
                                      unsigned long long a,
                                      unsigned long long b) {
    asm("fma.rn.f32x2 %0, %1, %2, %0;" : "+l"(d) : "l"(a), "l"(b));
}
__device__ __forceinline__ float ex2f(float x) {
    float r;
    asm("ex2.approx.ftz.f32 %0, %1;" : "=f"(r) : "f"(x));
    return r;
}
__device__ __forceinline__ float softplus20(float z) {
    return (z > 20.0f) ? z : fmaxf(z, 0.0f) + log1pf(__expf(-fabsf(z)));
}

// ---------- K1: split-K proj GEMM + As2 precompute ----------
// grid (64 ksplits of 80, 4 btiles of 64), block 256 = 8 warps, 2 CTAs/SM.
// Warp w handles 24 outputs; lane handles batches lane, lane+32.
#define K1_KC 80
#define K1_BT 64
#define K1_SMEM ((K1_KC * 65 + K1_KC * NOUT) * 4)

__global__ __launch_bounds__(256, 2)
void k1_proj(const float* __restrict__ x,
             const float* __restrict__ Wd,
             const float* __restrict__ WB,
             const float* __restrict__ WC,
             const float* __restrict__ Alog) {
    extern __shared__ float sm[];
    float* Xst = sm;                 // [k][b] 80 x 65 (pad)
    float* Ws  = sm + K1_KC * 65;    // [k][j] 80 x 192

    const int t    = threadIdx.x;
    const int cta  = blockIdx.y * gridDim.x + blockIdx.x;  // 0..255
    const int k0   = blockIdx.x * K1_KC;
    const int b0   = blockIdx.y * K1_BT;

    // As2 precompute: 256 CTAs x 320 elems (80 float4)
    if (t < 80) {
        int idx = cta * 320 + t * 4;
        float4 a = *(const float4*)&Alog[idx];
        const float c = -1.44269504088896f;
        float4 r;
        r.x = c * __expf(a.x); r.y = c * __expf(a.y);
        r.z = c * __expf(a.z); r.w = c * __expf(a.w);
        *(float4*)&g_As2[idx] = r;
    }

    // load X transposed: 64 rows x 20 quads
    for (int e = t; e < K1_BT * (K1_KC / 4); e += 256) {
        int row = e / 20;
        int q   = e - row * 20;
        float4 v = *(const float4*)&x[(b0 + row) * DIN + k0 + q * 4];
        int base = (q * 4) * 65 + row;
        Xst[base]       = v.x;
        Xst[base + 65]  = v.y;
        Xst[base + 130] = v.z;
        Xst[base + 195] = v.w;
    }
    // load W concatenated: 80 rows x 48 quads
    for (int e = t; e < K1_KC * 48; e += 256) {
        int k  = e / 48;
        int j4 = (e - k * 48) * 4;
        int kk = k0 + k;
        float4 v;
        if (j4 < RNK)      v = *(const float4*)&Wd[kk * RNK + j4];
        else if (j4 < 176) v = *(const float4*)&WB[kk * NST + (j4 - 160)];
        else               v = *(const float4*)&WC[kk * NST + (j4 - 176)];
        *(float4*)&Ws[k * NOUT + j4] = v;
    }
    __syncthreads();

    const int w    = t >> 5;
    const int lane = t & 31;
    const int jb   = w * 24;

    unsigned long long acc[2][12];
#pragma unroll
    for (int i = 0; i < 2; i++)
#pragma unroll
        for (int j = 0; j < 12; j++) acc[i][j] = 0ull;

#pragma unroll 2
    for (int k = 0; k < K1_KC; k++) {
        const ulonglong2* wp = (const ulonglong2*)&Ws[k * NOUT + jb];
        ulonglong2 w0 = wp[0], w1 = wp[1], w2 = wp[2];
        ulonglong2 w3 = wp[3], w4 = wp[4], w5 = wp[5];
        unsigned long long wr[12] = {w0.x, w0.y, w1.x, w1.y, w2.x, w2.y,
                                     w3.x, w3.y, w4.x, w4.y, w5.x, w5.y};
        float xa = Xst[k * 65 + lane];
        float xb = Xst[k * 65 + 32 + lane];
        unsigned long long xa2 = pack2(xa, xa);
        unsigned long long xb2 = pack2(xb, xb);
#pragma unroll
        for (int j = 0; j < 12; j++) {
            ffma2(acc[0][j], xa2, wr[j]);
            ffma2(acc[1][j], xb2, wr[j]);
        }
    }

#pragma unroll
    for (int j = 0; j < 12; j++) {
        float lo, hi;
        int jj = jb + j * 2;
        unpack2(acc[0][j], lo, hi);
        atomicAdd(&g_Pt[jj * BATCH + b0 + lane], lo);
        atomicAdd(&g_Pt[(jj + 1) * BATCH + b0 + lane], hi);
        unpack2(acc[1][j], lo, hi);
        atomicAdd(&g_Pt[jj * BATCH + b0 + 32 + lane], lo);
        atomicAdd(&g_Pt[(jj + 1) * BATCH + b0 + 32 + lane], hi);
    }
}

// ---------- K2: dt = softplus(P_low @ W_dt + b_dt); also Ct + SBC ----------
// grid (40 d-blocks of 128, 4 btiles of 64), block 256, 2 CTAs/SM = 1 wave.
// Each CTA processes two 64-d chunks reusing the Ps tile.
#define K2_SMEM ((RNK * 64 * 2) * 4)

__global__ __launch_bounds__(256, 2)
void k2_dt(const float* __restrict__ Wdt,
           const float* __restrict__ bdt) {
    extern __shared__ float sm[];
    float* Wds = sm;                 // [r][dj] 160 x 64
    float* Ps  = sm + RNK * 64;      // [r][bi] 160 x 64

    const int t  = threadIdx.x;
    const int b0 = blockIdx.y * 64;
    const int tx = t & 15;   // dj group of 4
    const int ty = t >> 4;   // bi group of 4

    // load P tile once
    for (int e = t; e < RNK * 16; e += 256) {
        int r = e >> 4, q = e & 15;
        *(float4*)&Ps[r * 64 + q * 4] = *(const float4*)&g_Pt[r * BATCH + b0 + q * 4];
    }

    for (int chunk = 0; chunk < 2; chunk++) {
        const int d0 = blockIdx.x * 128 + chunk * 64;
        __syncthreads();
        for (int e = t; e < RNK * 16; e += 256) {
            int r = e >> 4, q = e & 15;
            *(float4*)&Wds[r * 64 + q * 4] =
                *(const float4*)&Wdt[r * DIN + d0 + q * 4];
        }
        __syncthreads();

        unsigned long long acc[4][2];
#pragma unroll
        for (int i = 0; i < 4; i++) { acc[i][0] = 0ull; acc[i][1] = 0ull; }

#pragma unroll 2
        for (int r = 0; r < RNK; r++) {
            ulonglong2 wv = *(const ulonglong2*)&Wds[r * 64 + tx * 4];
            float4 p4 = *(const float4*)&Ps[r * 64 + ty * 4];
            float pv[4] = {p4.x, p4.y, p4.z, p4.w};
#pragma unroll
            for (int i = 0; i < 4; i++) {
                unsigned long long p2 = pack2(pv[i], pv[i]);
                ffma2(acc[i][0], p2, wv.x);
                ffma2(acc[i][1], p2, wv.y);
            }
        }

        float4 bb = *(const float4*)&bdt[d0 + tx * 4];
#pragma unroll
        for (int i = 0; i < 4; i++) {
            float z0, z1, z2, z3;
            unpack2(acc[i][0], z0, z1);
            unpack2(acc[i][1], z2, z3);
            float4 dt4;
            dt4.x = softplus20(z0 + bb.x);
            dt4.y = softplus20(z1 + bb.y);
            dt4.z = softplus20(z2 + bb.z);
            dt4.w = softplus20(z3 + bb.w);
            *(float4*)&g_dt[(b0 + ty * 4 + i) * DIN + d0 + tx * 4] = dt4;
        }
    }

    // first d-block column materializes Ct and SBC for its b-tile
    if (blockIdx.x == 0) {
        for (int e = t; e < 64 * NST; e += 256) {
            int bi = e >> 4, n = e & 15;
            g_Ct[(b0 + bi) * NST + n] = g_Pt[(176 + n) * BATCH + b0 + bi];
        }
        if (t < 64) {
            float s = 0.0f;
#pragma unroll
            for (int n = 0; n < NST; n++)
                s = fmaf(g_Pt[(160 + n) * BATCH + b0 + t],
                         g_Pt[(176 + n) * BATCH + b0 + t], s);
            g_SBC[b0 + t] = s;
        }
    }
}

// ---------- K3: stream h, produce y (warp-cooperative, coalesced) ----------
// group = (b, 8 consecutive d). 4 lanes per (b,d), lane q covers n = q*4..q*4+3.
#define NGRP (BATCH * DIN / 8)   // 163840
#define K3_GRID 1184

__global__ __launch_bounds__(256, 8)
void k3_stream(const float* __restrict__ h,
               const float* __restrict__ x,
               const float* __restrict__ Dv,
               float* __restrict__ out) {
    const int t     = threadIdx.x;
    const int lane  = t & 31;
    const int p     = lane >> 2;
    const int q     = lane & 3;
    const int wglob = blockIdx.x * 8 + (t >> 5);
    const int nw    = K3_GRID * 8;

    for (int g = wglob; g < NGRP; g += nw) {
        int b = g / 640;
        int c = g - b * 640;
        int d = c * 8 + p;

        float4 hv = *(const float4*)&h[((size_t)b * DIN + d) * NST + q * 4];
        float4 a4 = *(const float4*)&g_As2[d * NST + q * 4];
        float4 c4 = *(const float4*)&g_Ct[b * NST + q * 4];
        float dtv = g_dt[b * DIN + d];

        float e0 = ex2f(dtv * a4.x);
        float e1 = ex2f(dtv * a4.y);
        float e2 = ex2f(dtv * a4.z);
        float e3 = ex2f(dtv * a4.w);

        float s = c4.x * (e0 * hv.x);
        s = fmaf(c4.y, e1 * hv.y, s);
        s = fmaf(c4.z, e2 * hv.z, s);
        s = fmaf(c4.w, e3 * hv.w, s);

        s += __shfl_xor_sync(0xffffffffu, s, 1);
        s += __shfl_xor_sync(0xffffffffu, s, 2);

        if (q == 0) {
            float xv = x[b * DIN + d];
            float base = xv * fmaf(dtv, g_SBC[b], Dv[d]);
            out[b * DIN + d] = s + base;
        }
    }
}

// ---------- launch ----------
extern "C" void kernel_launch(void* const* d_in, const int* in_sizes, int n_in,
                              void* d_out, int out_size) {
    const float* x    = (const float*)d_in[0];
    const float* h    = (const float*)d_in[1];
    const float* Wd   = (const float*)d_in[2];
    const float* Wdt  = (const float*)d_in[3];
    const float* bdt  = (const float*)d_in[4];
    const float* Alog = (const float*)d_in[5];
    const float* WB   = (const float*)d_in[6];
    const float* WC   = (const float*)d_in[7];
    const float* Dv   = (const float*)d_in[8];
    float* out = (float*)d_out;

    cudaFuncSetAttribute(k1_proj, cudaFuncAttributeMaxDynamicSharedMemorySize, K1_SMEM);
    cudaFuncSetAttribute(k2_dt,   cudaFuncAttributeMaxDynamicSharedMemorySize, K2_SMEM);

    void* pt_ptr = nullptr;
    cudaGetSymbolAddress(&pt_ptr, g_Pt);
    cudaMemsetAsync(pt_ptr, 0, NOUT * BATCH * sizeof(float));

    k1_proj<<<dim3(DIN / K1_KC, BATCH / K1_BT), 256, K1_SMEM>>>(x, Wd, WB, WC, Alog);
    k2_dt<<<dim3(DIN / 128, BATCH / 64), 256, K2_SMEM>>>(Wdt, bdt);
    k3_stream<<<K3_GRID, 256>>>(h, x, Dv, out);
}

// round 5
// speedup vs baseline: 1.6432x; 1.0004x over previous
#include <cuda_runtime.h>
#include <cstdint>

#define BATCH   256
#define DIN     5120
#define RNK     160
#define NST     16
#define NOUT    192   // 160 (dt_low) + 16 (Bp) + 16 (C)

// Scratch
__device__ float g_Pt[NOUT * BATCH];        // P^T [out][batch]
__device__ float g_dt[BATCH * DIN];         // softplus'd delta [b][d]
__device__ float g_As2[DIN * NST];          // -exp(A_log)*log2e
__device__ float g_Ct[BATCH * NST];         // C transposed [b][n]
__device__ float g_SBC[BATCH];              // sum_n Bp*C per batch

// ---------- f32x2 helpers ----------
__device__ __forceinline__ unsigned long long pack2(float lo, float hi) {
    unsigned long long r;
    asm("mov.b64 %0, {%1, %2};" : "=l"(r)
        : "r"(__float_as_uint(lo)), "r"(__float_as_uint(hi)));
    return r;
}
__device__ __forceinline__ void unpack2(unsigned long long v, float& lo, float& hi) {
    unsigned int a, b;
    asm("mov.b64 {%0, %1}, %2;" : "=r"(a), "=r"(b) : "l"(v));
    lo = __uint_as_float(a);
    hi = __uint_as_float(b);
}
__device__ __forceinline__ void ffma2(unsigned long long& d,
                                      unsigned long long a,
                                      unsigned long long b) {
    asm("fma.rn.f32x2 %0, %1, %2, %0;" : "+l"(d) : "l"(a), "l"(b));
}
__device__ __forceinline__ float ex2f(float x) {
    float r;
    asm("ex2.approx.ftz.f32 %0, %1;" : "=f"(r) : "f"(x));
    return r;
}
__device__ __forceinline__ float softplus20(float z) {
    return (z > 20.0f) ? z : fmaxf(z, 0.0f) + log1pf(__expf(-fabsf(z)));
}

// ---------- K1: split-K proj GEMM + As2 precompute (pipelined) ----------
// grid (64 ksplits of 80, 4 btiles of 64), block 256 = 8 warps, 2 CTAs/SM.
// Warp w handles 24 outputs; lane handles batches lane, lane+32.
// Smem rows padded +2 so the register-pipeline epilogue prefetch stays in bounds.
// Ws offset rounded up to 16B alignment (ulonglong2 loads).
#define K1_KC 80
#define K1_BT 64
#define K1_XWORDS 5332                 // (80+2)*65 = 5330, rounded to mult of 4
#define K1_SMEM ((K1_XWORDS + (K1_KC + 2) * NOUT) * 4)

__global__ __launch_bounds__(256, 2)
void k1_proj(const float* __restrict__ x,
             const float* __restrict__ Wd,
             const float* __restrict__ WB,
             const float* __restrict__ WC,
             const float* __restrict__ Alog) {
    extern __shared__ float sm[];
    float* Xst = sm;                   // [k][b] (80+2) x 65
    float* Ws  = sm + K1_XWORDS;       // [k][j] (80+2) x 192, 16B aligned

    const int t    = threadIdx.x;
    const int cta  = blockIdx.y * gridDim.x + blockIdx.x;  // 0..255
    const int k0   = blockIdx.x * K1_KC;
    const int b0   = blockIdx.y * K1_BT;

    // As2 precompute: 256 CTAs x 320 elems (80 float4)
    if (t < 80) {
        int idx = cta * 320 + t * 4;
        float4 a = *(const float4*)&Alog[idx];
        const float c = -1.44269504088896f;
        float4 r;
        r.x = c * __expf(a.x); r.y = c * __expf(a.y);
        r.z = c * __expf(a.z); r.w = c * __expf(a.w);
        *(float4*)&g_As2[idx] = r;
    }

    // load X transposed: 64 rows x 20 quads
    for (int e = t; e < K1_BT * (K1_KC / 4); e += 256) {
        int row = e / 20;
        int q   = e - row * 20;
        float4 v = *(const float4*)&x[(b0 + row) * DIN + k0 + q * 4];
        int base = (q * 4) * 65 + row;
        Xst[base]       = v.x;
        Xst[base + 65]  = v.y;
        Xst[base + 130] = v.z;
        Xst[base + 195] = v.w;
    }
    // load W concatenated: 80 rows x 48 quads
    for (int e = t; e < K1_KC * 48; e += 256) {
        int k  = e / 48;
        int j4 = (e - k * 48) * 4;
        int kk = k0 + k;
        float4 v;
        if (j4 < RNK)      v = *(const float4*)&Wd[kk * RNK + j4];
        else if (j4 < 176) v = *(const float4*)&WB[kk * NST + (j4 - 160)];
        else               v = *(const float4*)&WC[kk * NST + (j4 - 176)];
        *(float4*)&Ws[k * NOUT + j4] = v;
    }
    __syncthreads();

    const int w    = t >> 5;
    const int lane = t & 31;
    const int jb   = w * 24;

    unsigned long long acc[2][12];
#pragma unroll
    for (int i = 0; i < 2; i++)
#pragma unroll
        for (int j = 0; j < 12; j++) acc[i][j] = 0ull;

    const float* wp = &Ws[jb];        // jb*4 = 96*w bytes, 16B aligned
    const float* xp = &Xst[lane];

    ulonglong2 WA[6], WBr[6];
    float xaA, xbA, xaB, xbB;
#pragma unroll
    for (int i = 0; i < 6; i++) WA[i] = ((const ulonglong2*)wp)[i];
    xaA = xp[0]; xbA = xp[32];

#pragma unroll 1
    for (int k = 0; k < K1_KC; k += 2) {
        // prefetch stage B (row k+1)
        const float* wpn = wp + NOUT;
#pragma unroll
        for (int i = 0; i < 6; i++) WBr[i] = ((const ulonglong2*)wpn)[i];
        xaB = xp[65]; xbB = xp[97];

        // compute stage A (row k)
        {
            unsigned long long x2a = pack2(xaA, xaA);
            unsigned long long x2b = pack2(xbA, xbA);
#pragma unroll
            for (int i = 0; i < 6; i++) {
                ffma2(acc[0][2*i],   x2a, WA[i].x);
                ffma2(acc[0][2*i+1], x2a, WA[i].y);
                ffma2(acc[1][2*i],   x2b, WA[i].x);
                ffma2(acc[1][2*i+1], x2b, WA[i].y);
            }
        }

        wp += 2 * NOUT; xp += 130;
        // prefetch stage A (row k+2; pad rows make this safe at k=78)
#pragma unroll
        for (int i = 0; i < 6; i++) WA[i] = ((const ulonglong2*)wp)[i];
        xaA = xp[0]; xbA = xp[32];

        // compute stage B (row k+1)
        {
            unsigned long long x2a = pack2(xaB, xaB);
            unsigned long long x2b = pack2(xbB, xbB);
#pragma unroll
            for (int i = 0; i < 6; i++) {
                ffma2(acc[0][2*i],   x2a, WBr[i].x);
                ffma2(acc[0][2*i+1], x2a, WBr[i].y);
                ffma2(acc[1][2*i],   x2b, WBr[i].x);
                ffma2(acc[1][2*i+1], x2b, WBr[i].y);
            }
        }
    }

#pragma unroll
    for (int j = 0; j < 12; j++) {
        float lo, hi;
        int jj = jb + j * 2;
        unpack2(acc[0][j], lo, hi);
        atomicAdd(&g_Pt[jj * BATCH + b0 + lane], lo);
        atomicAdd(&g_Pt[(jj + 1) * BATCH + b0 + lane], hi);
        unpack2(acc[1][j], lo, hi);
        atomicAdd(&g_Pt[jj * BATCH + b0 + 32 + lane], lo);
        atomicAdd(&g_Pt[(jj + 1) * BATCH + b0 + 32 + lane], hi);
    }
}

// ---------- K2: dt = softplus(P_low @ W_dt + b_dt); also Ct + SBC (pipelined) ----------
// grid (40 d-blocks of 128, 4 btiles of 64), block 256, 2 CTAs/SM.
// Each CTA processes two 64-d chunks reusing the Ps tile. +1 pad row per array
// (64-float rows keep 16B alignment).
#define K2_SMEM (((RNK + 1) * 64 * 2) * 4)

__global__ __launch_bounds__(256, 2)
void k2_dt(const float* __restrict__ Wdt,
           const float* __restrict__ bdt) {
    extern __shared__ float sm[];
    float* Wds = sm;                      // [r][dj] (160+1) x 64
    float* Ps  = sm + (RNK + 1) * 64;     // [r][bi] (160+1) x 64

    const int t  = threadIdx.x;
    const int b0 = blockIdx.y * 64;
    const int tx = t & 15;   // dj group of 4
    const int ty = t >> 4;   // bi group of 4

    // load P tile once
    for (int e = t; e < RNK * 16; e += 256) {
        int r = e >> 4, q = e & 15;
        *(float4*)&Ps[r * 64 + q * 4] = *(const float4*)&g_Pt[r * BATCH + b0 + q * 4];
    }

    for (int chunk = 0; chunk < 2; chunk++) {
        const int d0 = blockIdx.x * 128 + chunk * 64;
        __syncthreads();
        for (int e = t; e < RNK * 16; e += 256) {
            int r = e >> 4, q = e & 15;
            *(float4*)&Wds[r * 64 + q * 4] =
                *(const float4*)&Wdt[r * DIN + d0 + q * 4];
        }
        __syncthreads();

        unsigned long long acc[4][2];
#pragma unroll
        for (int i = 0; i < 4; i++) { acc[i][0] = 0ull; acc[i][1] = 0ull; }

        const float* wrow = &Wds[tx * 4];
        const float* prow = &Ps[ty * 4];
        ulonglong2 WAr = *(const ulonglong2*)wrow;
        float4     PAr = *(const float4*)prow;

#pragma unroll 1
        for (int r = 0; r < RNK; r += 2) {
            ulonglong2 WBr = *(const ulonglong2*)(wrow + 64);
            float4     PBr = *(const float4*)(prow + 64);
            {
                unsigned long long p0 = pack2(PAr.x, PAr.x);
                unsigned long long p1 = pack2(PAr.y, PAr.y);
                unsigned long long p2 = pack2(PAr.z, PAr.z);
                unsigned long long p3 = pack2(PAr.w, PAr.w);
                ffma2(acc[0][0], p0, WAr.x); ffma2(acc[0][1], p0, WAr.y);
                ffma2(acc[1][0], p1, WAr.x); ffma2(acc[1][1], p1, WAr.y);
                ffma2(acc[2][0], p2, WAr.x); ffma2(acc[2][1], p2, WAr.y);
                ffma2(acc[3][0], p3, WAr.x); ffma2(acc[3][1], p3, WAr.y);
            }
            wrow += 128; prow += 128;
            WAr = *(const ulonglong2*)wrow;      // pad row safe at r=158
            PAr = *(const float4*)prow;
            {
                unsigned long long p0 = pack2(PBr.x, PBr.x);
                unsigned long long p1 = pack2(PBr.y, PBr.y);
                unsigned long long p2 = pack2(PBr.z, PBr.z);
                unsigned long long p3 = pack2(PBr.w, PBr.w);
                ffma2(acc[0][0], p0, WBr.x); ffma2(acc[0][1], p0, WBr.y);
                ffma2(acc[1][0], p1, WBr.x); ffma2(acc[1][1], p1, WBr.y);
                ffma2(acc[2][0], p2, WBr.x); ffma2(acc[2][1], p2, WBr.y);
                ffma2(acc[3][0], p3, WBr.x); ffma2(acc[3][1], p3, WBr.y);
            }
        }

        float4 bb = *(const float4*)&bdt[d0 + tx * 4];
#pragma unroll
        for (int i = 0; i < 4; i++) {
            float z0, z1, z2, z3;
            unpack2(acc[i][0], z0, z1);
            unpack2(acc[i][1], z2, z3);
            float4 dt4;
            dt4.x = softplus20(z0 + bb.x);
            dt4.y = softplus20(z1 + bb.y);
            dt4.z = softplus20(z2 + bb.z);
            dt4.w = softplus20(z3 + bb.w);
            *(float4*)&g_dt[(b0 + ty * 4 + i) * DIN + d0 + tx * 4] = dt4;
        }
    }

    // first d-block column materializes Ct and SBC for its b-tile
    if (blockIdx.x == 0) {
        for (int e = t; e < 64 * NST; e += 256) {
            int bi = e >> 4, n = e & 15;
            g_Ct[(b0 + bi) * NST + n] = g_Pt[(176 + n) * BATCH + b0 + bi];
        }
        if (t < 64) {
            float s = 0.0f;
#pragma unroll
            for (int n = 0; n < NST; n++)
                s = fmaf(g_Pt[(160 + n) * BATCH + b0 + t],
                         g_Pt[(176 + n) * BATCH + b0 + t], s);
            g_SBC[b0 + t] = s;
        }
    }
}

// ---------- K3: stream h, produce y (warp-cooperative, coalesced) ----------
// group = (b, 8 consecutive d). 4 lanes per (b,d), lane q covers n = q*4..q*4+3.
#define NGRP (BATCH * DIN / 8)   // 163840
#define K3_GRID 1184

__global__ __launch_bounds__(256, 8)
void k3_stream(const float* __restrict__ h,
               const float* __restrict__ x,
               const float* __restrict__ Dv,
               float* __restrict__ out) {
    const int t     = threadIdx.x;
    const int lane  = t & 31;
    const int p     = lane >> 2;
    const int q     = lane & 3;
    const int wglob = blockIdx.x * 8 + (t >> 5);
    const int nw    = K3_GRID * 8;

    for (int g = wglob; g < NGRP; g += nw) {
        int b = g / 640;
        int c = g - b * 640;
        int d = c * 8 + p;

        float4 hv = *(const float4*)&h[((size_t)b * DIN + d) * NST + q * 4];
        float4 a4 = *(const float4*)&g_As2[d * NST + q * 4];
        float4 c4 = *(const float4*)&g_Ct[b * NST + q * 4];
        float dtv = g_dt[b * DIN + d];

        float e0 = ex2f(dtv * a4.x);
        float e1 = ex2f(dtv * a4.y);
        float e2 = ex2f(dtv * a4.z);
        float e3 = ex2f(dtv * a4.w);

        float s = c4.x * (e0 * hv.x);
        s = fmaf(c4.y, e1 * hv.y, s);
        s = fmaf(c4.z, e2 * hv.z, s);
        s = fmaf(c4.w, e3 * hv.w, s);

        s += __shfl_xor_sync(0xffffffffu, s, 1);
        s += __shfl_xor_sync(0xffffffffu, s, 2);

        if (q == 0) {
            float xv = x[b * DIN + d];
            float base = xv * fmaf(dtv, g_SBC[b], Dv[d]);
            out[b * DIN + d] = s + base;
        }
    }
}

// ---------- launch ----------
extern "C" void kernel_launch(void* const* d_in, const int* in_sizes, int n_in,
                              void* d_out, int out_size) {
    const float* x    = (const float*)d_in[0];
    const float* h    = (const float*)d_in[1];
    const float* Wd   = (const float*)d_in[2];
    const float* Wdt  = (const float*)d_in[3];
    const float* bdt  = (const float*)d_in[4];
    const float* Alog = (const float*)d_in[5];
    const float* WB   = (const float*)d_in[6];
    const float* WC   = (const float*)d_in[7];
    const float* Dv   = (const float*)d_in[8];
    float* out = (float*)d_out;

    cudaFuncSetAttribute(k1_proj, cudaFuncAttributeMaxDynamicSharedMemorySize, K1_SMEM);
    cudaFuncSetAttribute(k2_dt,   cudaFuncAttributeMaxDynamicSharedMemorySize, K2_SMEM);

    void* pt_ptr = nullptr;
    cudaGetSymbolAddress(&pt_ptr, g_Pt);
    cudaMemsetAsync(pt_ptr, 0, NOUT * BATCH * sizeof(float));

    k1_proj<<<dim3(DIN / K1_KC, BATCH / K1_BT), 256, K1_SMEM>>>(x, Wd, WB, WC, Alog);
    k2_dt<<<dim3(DIN / 128, BATCH / 64), 256, K2_SMEM>>>(Wdt, bdt);
    k3_stream<<<K3_GRID, 256>>>(h, x, Dv, out);
}